// round 2
// baseline (speedup 1.0000x reference)
#include <cuda_runtime.h>
#include <cstdint>
#include <math.h>

#define Nn 8192
#define Dd 128
#define BM 64
#define BN 64
#define NBLK (Nn / BM)   // 128

// Scratch (allocation-free rule: __device__ globals)
__device__ float g_Zt[Dd * Nn];        // normalized Z, transposed: [k][n], 4 MB
__device__ float g_blockLoss[NBLK];    // per-block partial loss sums

// ---------------------------------------------------------------------------
// Kernel 1: row-normalize and write transposed Z (k-major) so the GEMM tile
// loads are coalesced AND bank-conflict-free.
// One warp per row. blockDim = (32, 8).
// ---------------------------------------------------------------------------
__global__ void __launch_bounds__(256) normalize_T_kernel(const float* __restrict__ x) {
    const int row  = blockIdx.x * 8 + threadIdx.y;
    const int lane = threadIdx.x;
    // coalesced float4 read of this row
    float4 v = reinterpret_cast<const float4*>(x)[row * (Dd / 4) + lane];
    float ss = v.x * v.x + v.y * v.y + v.z * v.z + v.w * v.w;
    #pragma unroll
    for (int o = 16; o; o >>= 1) ss += __shfl_xor_sync(0xffffffffu, ss, o);
    const float inv = 1.0f / fmaxf(sqrtf(ss), 1e-8f);
    const int k0 = lane * 4;
    // scattered stores (one-time, 4 MB total) into transposed layout
    g_Zt[(k0 + 0) * Nn + row] = v.x * inv;
    g_Zt[(k0 + 1) * Nn + row] = v.y * inv;
    g_Zt[(k0 + 2) * Nn + row] = v.z * inv;
    g_Zt[(k0 + 3) * Nn + row] = v.w * inv;
}

// ---------------------------------------------------------------------------
// Kernel 2: fused sim-GEMM + online logsumexp (flash-style).
// Grid: 128 blocks, each owns 64 rows. Loop over 128 column tiles of 64.
// blockDim (16,16); each thread computes a 4x4 sim sub-tile via packed
// fma.rn.f32x2 (FFMA2, 2x fp32 FMA throughput on sm_103a).
// Never materializes the 256 MB sim matrix.
// ---------------------------------------------------------------------------
__global__ void __launch_bounds__(256) ntxent_fused_kernel() {
    extern __shared__ float sh[];
    float* As = sh;               // [Dd][BM] k-major
    float* Bs = sh + Dd * BM;     // [Dd][BN] k-major

    const int tx  = threadIdx.x;             // 0..15  -> 4 columns
    const int ty  = threadIdx.y;             // 0..15  -> 4 rows
    const int tid = ty * 16 + tx;
    const int rowBase = blockIdx.x * BM;

    // Load A tile once (rows fixed for this block). Zt is k-major, so each
    // pass reads contiguous 256B segments (coalesced) and stores consecutive
    // floats into smem (conflict-free).
    #pragma unroll
    for (int p = 0; p < 8; ++p) {
        int idx = p * 256 + tid;
        int k   = idx >> 4;       // 0..127
        int m4  = idx & 15;       // float4 slot along m
        float4 g = *reinterpret_cast<const float4*>(&g_Zt[k * Nn + rowBase + m4 * 4]);
        *reinterpret_cast<float4*>(&As[k * BM + m4 * 4]) = g;
    }

    float m[4], s[4], pos[4];
    #pragma unroll
    for (int r = 0; r < 4; ++r) { m[r] = -1e30f; s[r] = 0.0f; pos[r] = 0.0f; }

    const int grow0 = rowBase + ty * 4;

    for (int t = 0; t < Nn / BN; ++t) {
        const int colBase = t * BN;
        __syncthreads();   // previous tile's compute done before overwriting Bs
        #pragma unroll
        for (int p = 0; p < 8; ++p) {
            int idx = p * 256 + tid;
            int k   = idx >> 4;
            int m4  = idx & 15;
            float4 g = *reinterpret_cast<const float4*>(&g_Zt[k * Nn + colBase + m4 * 4]);
            *reinterpret_cast<float4*>(&Bs[k * BN + m4 * 4]) = g;
        }
        __syncthreads();

        // ---- 64x64 tile GEMM, 4x4 per thread, packed f32x2 accumulators ----
        unsigned long long acc[4][2];
        #pragma unroll
        for (int r = 0; r < 4; ++r) { acc[r][0] = 0ull; acc[r][1] = 0ull; }

        #pragma unroll 16
        for (int k = 0; k < Dd; ++k) {
            float4 a = *reinterpret_cast<const float4*>(&As[k * BM + ty * 4]);
            ulonglong2 b = *reinterpret_cast<const ulonglong2*>(&Bs[k * BN + tx * 4]);
            unsigned long long a0, a1, a2, a3;
            asm("mov.b64 %0, {%1, %1};" : "=l"(a0) : "f"(a.x));
            asm("mov.b64 %0, {%1, %1};" : "=l"(a1) : "f"(a.y));
            asm("mov.b64 %0, {%1, %1};" : "=l"(a2) : "f"(a.z));
            asm("mov.b64 %0, {%1, %1};" : "=l"(a3) : "f"(a.w));
            asm("fma.rn.f32x2 %0, %1, %2, %0;" : "+l"(acc[0][0]) : "l"(a0), "l"(b.x));
            asm("fma.rn.f32x2 %0, %1, %2, %0;" : "+l"(acc[0][1]) : "l"(a0), "l"(b.y));
            asm("fma.rn.f32x2 %0, %1, %2, %0;" : "+l"(acc[1][0]) : "l"(a1), "l"(b.x));
            asm("fma.rn.f32x2 %0, %1, %2, %0;" : "+l"(acc[1][1]) : "l"(a1), "l"(b.y));
            asm("fma.rn.f32x2 %0, %1, %2, %0;" : "+l"(acc[2][0]) : "l"(a2), "l"(b.x));
            asm("fma.rn.f32x2 %0, %1, %2, %0;" : "+l"(acc[2][1]) : "l"(a2), "l"(b.y));
            asm("fma.rn.f32x2 %0, %1, %2, %0;" : "+l"(acc[3][0]) : "l"(a3), "l"(b.x));
            asm("fma.rn.f32x2 %0, %1, %2, %0;" : "+l"(acc[3][1]) : "l"(a3), "l"(b.y));
        }

        // ---- epilogue: scale 1/T, diag mask, positive capture, online LSE ----
        #pragma unroll
        for (int r = 0; r < 4; ++r) {
            float v0, v1, v2, v3;
            asm("mov.b64 {%0, %1}, %2;" : "=f"(v0), "=f"(v1) : "l"(acc[r][0]));
            asm("mov.b64 {%0, %1}, %2;" : "=f"(v2), "=f"(v3) : "l"(acc[r][1]));
            v0 *= 10.0f; v1 *= 10.0f; v2 *= 10.0f; v3 *= 10.0f;  // /TEMPERATURE

            const int grow = grow0 + r;
            const int gcol = colBase + tx * 4;
            const int pc   = (grow + Nn / 2) & (Nn - 1);   // positive column

            if (gcol + 0 == grow) v0 = -1e30f;   // diagonal -> effectively -inf
            if (gcol + 1 == grow) v1 = -1e30f;
            if (gcol + 2 == grow) v2 = -1e30f;
            if (gcol + 3 == grow) v3 = -1e30f;

            if (gcol + 0 == pc) pos[r] += v0;
            if (gcol + 1 == pc) pos[r] += v1;
            if (gcol + 2 == pc) pos[r] += v2;
            if (gcol + 3 == pc) pos[r] += v3;

            const float tm = fmaxf(fmaxf(v0, v1), fmaxf(v2, v3));
            const float nm = fmaxf(m[r], tm);
            const float e  = __expf(v0 - nm) + __expf(v1 - nm)
                           + __expf(v2 - nm) + __expf(v3 - nm);
            s[r] = s[r] * __expf(m[r] - nm) + e;
            m[r] = nm;
        }
    }

    // ---- reduce (m,s,pos) across the 16 tx-lanes of each row (butterfly) ----
    #pragma unroll
    for (int r = 0; r < 4; ++r) {
        #pragma unroll
        for (int o = 8; o; o >>= 1) {
            float om = __shfl_xor_sync(0xffffffffu, m[r],  o);
            float os = __shfl_xor_sync(0xffffffffu, s[r],  o);
            float op = __shfl_xor_sync(0xffffffffu, pos[r], o);
            float nm = fmaxf(m[r], om);
            s[r]   = s[r] * __expf(m[r] - nm) + os * __expf(om - nm);
            m[r]   = nm;
            pos[r] += op;
        }
    }

    __shared__ float red[16];
    if (tx == 0) {
        float lsum = 0.0f;
        #pragma unroll
        for (int r = 0; r < 4; ++r) lsum += m[r] + logf(s[r]) - pos[r];
        red[ty] = lsum;
    }
    __syncthreads();
    if (tid == 0) {
        float tot = 0.0f;
        #pragma unroll
        for (int i = 0; i < 16; ++i) tot += red[i];
        g_blockLoss[blockIdx.x] = tot;   // deterministic: no float atomics
    }
}

// ---------------------------------------------------------------------------
// Kernel 3: deterministic final reduction -> mean loss scalar
// ---------------------------------------------------------------------------
__global__ void __launch_bounds__(128) finalize_kernel(float* __restrict__ out) {
    __shared__ float red[NBLK];
    const int t = threadIdx.x;
    red[t] = g_blockLoss[t];
    __syncthreads();
    #pragma unroll
    for (int o = 64; o; o >>= 1) {
        if (t < o) red[t] += red[t + o];
        __syncthreads();
    }
    if (t == 0) out[0] = red[0] / (float)Nn;
}

// ---------------------------------------------------------------------------
extern "C" void kernel_launch(void* const* d_in, const int* in_sizes, int n_in,
                              void* d_out, int out_size) {
    const float* x  = (const float*)d_in[0];
    float* out      = (float*)d_out;
    (void)in_sizes; (void)n_in; (void)out_size;

    const size_t smem = 2 * Dd * BM * sizeof(float);   // 64 KB dynamic
    cudaFuncSetAttribute(ntxent_fused_kernel,
                         cudaFuncAttributeMaxDynamicSharedMemorySize, (int)smem);

    normalize_T_kernel<<<Nn / 8, dim3(32, 8)>>>(x);
    ntxent_fused_kernel<<<NBLK, dim3(16, 16), smem>>>();
    finalize_kernel<<<1, 128>>>(out);
}

// round 8
// speedup vs baseline: 5.9499x; 5.9499x over previous
#include <cuda_runtime.h>
#include <cuda_bf16.h>
#include <cstdint>
#include <math.h>

#define Nn 8192
#define Dd 128
#define TM 128                     // rows per CTA
#define TN 128                     // cols per tile
#define NHALF 2
#define COLS_PER_CTA (Nn / NHALF)  // 4096
#define NTILES (COLS_PER_CTA / TN) // 32
#define NRB (Nn / TM)              // 64 row blocks

// __device__ globals (allocation-free scratch)
__device__ float          g_zf[Nn * Dd];     // normalized rows fp32 (exact pos)
__device__ __nv_bfloat16  g_zb[Nn * Dd];     // normalized rows bf16 (MMA operand)
__device__ float          g_S[2 * Nn];       // per-row partial sums (2 col halves)
__device__ float          g_pos[Nn];
__device__ float          g_partial[NRB];

// ---------------------------------------------------------------------------
// helpers (all base-sm_103-safe PTX: cp.async, ldmatrix, mma.sync, f32x2)
// ---------------------------------------------------------------------------
__device__ __forceinline__ uint32_t smem_u32(const void* p) {
    uint32_t a;
    asm("{ .reg .u64 t; cvta.to.shared.u64 t, %1; cvt.u32.u64 %0, t; }"
        : "=r"(a) : "l"(p));
    return a;
}
__device__ __forceinline__ void cpasync16(uint32_t dst, const void* src) {
    asm volatile("cp.async.cg.shared.global [%0], [%1], 16;"
                 :: "r"(dst), "l"(src) : "memory");
}
__device__ __forceinline__ void ldsm4(uint32_t* r, uint32_t addr) {
    asm volatile("ldmatrix.sync.aligned.m8n8.x4.shared.b16 {%0,%1,%2,%3}, [%4];"
                 : "=r"(r[0]), "=r"(r[1]), "=r"(r[2]), "=r"(r[3]) : "r"(addr));
}
__device__ __forceinline__ void mma16816(float* c, const uint32_t* a,
                                         uint32_t b0, uint32_t b1) {
    asm volatile(
        "mma.sync.aligned.m16n8k16.row.col.f32.bf16.bf16.f32 "
        "{%0,%1,%2,%3}, {%4,%5,%6,%7}, {%8,%9}, {%0,%1,%2,%3};"
        : "+f"(c[0]), "+f"(c[1]), "+f"(c[2]), "+f"(c[3])
        : "r"(a[0]), "r"(a[1]), "r"(a[2]), "r"(a[3]), "r"(b0), "r"(b1));
}
__device__ __forceinline__ unsigned long long pack2(float a, float b) {
    unsigned long long r;
    asm("mov.b64 %0, {%1,%2};" : "=l"(r) : "f"(a), "f"(b));
    return r;
}

// ---------------------------------------------------------------------------
// Kernel 1: normalize rows -> fp32 + bf16 (row-major, coalesced)
// ---------------------------------------------------------------------------
__global__ void __launch_bounds__(256) normalize_kernel(const float* __restrict__ x) {
    const int row  = blockIdx.x * 8 + threadIdx.y;
    const int lane = threadIdx.x;
    float4 v = reinterpret_cast<const float4*>(x)[row * 32 + lane];
    float ss = v.x * v.x + v.y * v.y + v.z * v.z + v.w * v.w;
    #pragma unroll
    for (int o = 16; o; o >>= 1) ss += __shfl_xor_sync(0xffffffffu, ss, o);
    const float inv = 1.0f / fmaxf(sqrtf(ss), 1e-8f);
    float4 z = make_float4(v.x * inv, v.y * inv, v.z * inv, v.w * inv);
    reinterpret_cast<float4*>(g_zf)[row * 32 + lane] = z;
    __nv_bfloat162 b0 = __floats2bfloat162_rn(z.x, z.y);
    __nv_bfloat162 b1 = __floats2bfloat162_rn(z.z, z.w);
    uint2 u;
    u.x = *reinterpret_cast<uint32_t*>(&b0);
    u.y = *reinterpret_cast<uint32_t*>(&b1);
    reinterpret_cast<uint2*>(g_zb)[row * 32 + lane] = u;
}

// ---------------------------------------------------------------------------
// Kernel 2: exact fp32 positive dots: pos[i] = 10 * dot(z_i, z_{i+N/2})
// ---------------------------------------------------------------------------
__global__ void __launch_bounds__(256) pos_kernel() {
    const int wid  = threadIdx.x >> 5;
    const int lane = threadIdx.x & 31;
    const int row  = blockIdx.x * 8 + wid;
    const int prow = (row + Nn / 2) & (Nn - 1);
    float4 a = reinterpret_cast<const float4*>(g_zf)[row * 32 + lane];
    float4 b = reinterpret_cast<const float4*>(g_zf)[prow * 32 + lane];
    float d = a.x * b.x + a.y * b.y + a.z * b.z + a.w * b.w;
    #pragma unroll
    for (int o = 16; o; o >>= 1) d += __shfl_xor_sync(0xffffffffu, d, o);
    if (lane == 0) g_pos[row] = d * 10.0f;
}

// ---------------------------------------------------------------------------
// Main kernel: mma.sync bf16 Gram GEMM + MUFU-free packed-exp2 epilogue
// ---------------------------------------------------------------------------
struct EC {
    unsigned long long C1, C0, MG, N1, P5, P4, P3, P2, P1, P0;
};

// sum2 += exp(10*x0 - 10), exp(10*x1 - 10) packed; optionally zero diag elems.
template <bool MASKED>
__device__ __forceinline__ void expacc(float x0, float x1,
                                       unsigned long long& sum2,
                                       int R, int C, const EC& c) {
    unsigned long long v2 = pack2(x0, x1);
    unsigned long long t2, zi2, fzi2, f2, p2, r2;
    asm("fma.rn.f32x2 %0, %1, %2, %3;" : "=l"(t2)  : "l"(v2),   "l"(c.C1), "l"(c.C0));
    asm("add.rn.f32x2 %0, %1, %2;"     : "=l"(zi2) : "l"(t2),   "l"(c.MG));
    asm("fma.rn.f32x2 %0, %1, %2, %3;" : "=l"(fzi2): "l"(c.MG), "l"(c.N1), "l"(zi2));
    asm("fma.rn.f32x2 %0, %1, %2, %3;" : "=l"(f2)  : "l"(fzi2), "l"(c.N1), "l"(t2));
    asm("fma.rn.f32x2 %0, %1, %2, %3;" : "=l"(p2)  : "l"(c.P5), "l"(f2),   "l"(c.P4));
    asm("fma.rn.f32x2 %0, %1, %2, %3;" : "=l"(p2)  : "l"(p2),   "l"(f2),   "l"(c.P3));
    asm("fma.rn.f32x2 %0, %1, %2, %3;" : "=l"(p2)  : "l"(p2),   "l"(f2),   "l"(c.P2));
    asm("fma.rn.f32x2 %0, %1, %2, %3;" : "=l"(p2)  : "l"(p2),   "l"(f2),   "l"(c.P1));
    asm("fma.rn.f32x2 %0, %1, %2, %3;" : "=l"(p2)  : "l"(p2),   "l"(f2),   "l"(c.P0));
    uint32_t zlo, zhi, plo, phi;
    asm("mov.b64 {%0,%1}, %2;" : "=r"(zlo), "=r"(zhi) : "l"(zi2));
    asm("mov.b64 {%0,%1}, %2;" : "=r"(plo), "=r"(phi) : "l"(p2));
    uint32_t rlo = plo + (zlo << 23);   // exponent insert (magic low bits = round(t))
    uint32_t rhi = phi + (zhi << 23);
    if (MASKED) {
        if (R == C)     rlo = 0u;
        if (R == C + 1) rhi = 0u;
    }
    asm("mov.b64 %0, {%1,%2};" : "=l"(r2) : "r"(rlo), "r"(rhi));
    asm("add.rn.f32x2 %0, %1, %2;" : "=l"(sum2) : "l"(sum2), "l"(r2));
}

// cp.async one 128x128 bf16 tile (row-major, 256B/row) into swizzled smem:
// 16B chunk c of row r goes to chunk (c ^ (r & 7))  -> ldmatrix conflict-free.
__device__ __forceinline__ void load_tile(uint32_t sbase,
                                          const __nv_bfloat16* src, int tid) {
    #pragma unroll
    for (int p = 0; p < 8; ++p) {
        int idx = p * 256 + tid;
        int r = idx >> 4;
        int c = idx & 15;
        cpasync16(sbase + (uint32_t)(r * 256 + ((c ^ (r & 7)) << 4)),
                  (const void*)(src + r * Dd + c * 8));
    }
}

__device__ __forceinline__ uint32_t tile_addr(uint32_t sbase, int row, int ch) {
    return sbase + (uint32_t)(row * 256 + ((ch ^ (row & 7)) << 4));
}

__global__ void __launch_bounds__(256, 1) ntxent_mma_kernel() {
    extern __shared__ __align__(16) unsigned char dyn[];
    __shared__ float s_part[2][TM];

    const int tid  = threadIdx.x;
    const int w    = tid >> 5;
    const int lane = tid & 31;
    const int wm   = w & 3;        // row group (32 rows each)
    const int wn   = w >> 2;       // col group (64 cols each)
    const int bid  = blockIdx.x;
    const int rb   = bid & (NRB - 1);
    const int half = bid >> 6;
    const int rowBase  = rb << 7;
    const int colBase0 = half << 12;
    const int tDiag = ((rb >> 5) == half) ? (rb & 31) : -1;

    const uint32_t sA  = smem_u32(dyn);
    const uint32_t sB0 = sA + 32768u;
    const uint32_t sB1 = sA + 65536u;

    // Kick off A and B0 loads.
    load_tile(sA, g_zb + (size_t)rowBase * Dd, tid);
    asm volatile("cp.async.commit_group;" ::: "memory");
    load_tile(sB0, g_zb + (size_t)colBase0 * Dd, tid);
    asm volatile("cp.async.commit_group;" ::: "memory");

    // exp(10v-10) = exp2(v*L - L), L = 10*log2(e)
    EC c;
    const float L = 14.4269504088896341f;
    c.C1 = pack2(L, L);   c.C0 = pack2(-L, -L);
    c.MG = pack2(12582912.0f, 12582912.0f);     // 1.5 * 2^23
    c.N1 = pack2(-1.0f, -1.0f);
    c.P5 = pack2(1.33335581e-3f, 1.33335581e-3f);
    c.P4 = pack2(9.61812911e-3f, 9.61812911e-3f);
    c.P3 = pack2(5.55041087e-2f, 5.55041087e-2f);
    c.P2 = pack2(2.40226507e-1f, 2.40226507e-1f);
    c.P1 = pack2(6.93147181e-1f, 6.93147181e-1f);
    c.P0 = pack2(1.0f, 1.0f);

    // Wait for A, preload all A fragments into registers (held for all tiles).
    asm volatile("cp.async.wait_group 1;" ::: "memory");
    __syncthreads();
    uint32_t Af[2][8][4];
    #pragma unroll
    for (int mf = 0; mf < 2; ++mf) {
        const int arow = wm * 32 + mf * 16 + (lane & 15);
        #pragma unroll
        for (int k = 0; k < 8; ++k)
            ldsm4(Af[mf][k], tile_addr(sA, arow, 2 * k + (lane >> 4)));
    }

    unsigned long long rs[2][2];   // packed row sums: [mf][lo/hi]
    rs[0][0] = rs[0][1] = rs[1][0] = rs[1][1] = 0ull;

    const int Rl = lane >> 2;            // row-in-frag low
    const int Cl = (lane & 3) * 2;       // col-in-frag

    for (int t = 0; t < NTILES; ++t) {
        asm volatile("cp.async.wait_group 0;" ::: "memory");
        __syncthreads();                 // B[t] visible; prev buf reads done
        if (t + 1 < NTILES) {
            load_tile((t & 1) ? sB0 : sB1,
                      g_zb + (size_t)(colBase0 + (t + 1) * TN) * Dd, tid);
            asm volatile("cp.async.commit_group;" ::: "memory");
        }
        const uint32_t sBt = (t & 1) ? sB1 : sB0;
        const bool diagT = (t == tDiag);
        const int tileCol = colBase0 + t * TN;

        #pragma unroll
        for (int p = 0; p < 4; ++p) {    // 16-col pair group within warp's 64
            float acc[2][2][4];
            #pragma unroll
            for (int i = 0; i < 2; ++i)
                #pragma unroll
                for (int j = 0; j < 2; ++j)
                    acc[i][j][0] = acc[i][j][1] = acc[i][j][2] = acc[i][j][3] = 0.0f;

            const int brow = wn * 64 + p * 16 + (lane & 15);
            #pragma unroll
            for (int k = 0; k < 8; ++k) {
                uint32_t b[4];
                ldsm4(b, tile_addr(sBt, brow, 2 * k + (lane >> 4)));
                mma16816(acc[0][0], Af[0][k], b[0], b[2]);
                mma16816(acc[0][1], Af[0][k], b[1], b[3]);
                mma16816(acc[1][0], Af[1][k], b[0], b[2]);
                mma16816(acc[1][1], Af[1][k], b[1], b[3]);
            }

            // epilogue: exp + row-sum accumulate (diag tile masks col==row)
            #pragma unroll
            for (int mf = 0; mf < 2; ++mf) {
                #pragma unroll
                for (int nh = 0; nh < 2; ++nh) {
                    const float* a = acc[mf][nh];
                    if (diagT) {
                        const int R0 = rowBase + wm * 32 + mf * 16 + Rl;
                        const int C0 = tileCol + wn * 64 + p * 16 + nh * 8 + Cl;
                        expacc<true >(a[0], a[1], rs[mf][0], R0,     C0, c);
                        expacc<true >(a[2], a[3], rs[mf][1], R0 + 8, C0, c);
                    } else {
                        expacc<false>(a[0], a[1], rs[mf][0], 0, 0, c);
                        expacc<false>(a[2], a[3], rs[mf][1], 0, 0, c);
                    }
                }
            }
        }
    }

    // Reduce: packed halves -> scalar, then across the 4 lanes sharing a row.
    #pragma unroll
    for (int mf = 0; mf < 2; ++mf) {
        #pragma unroll
        for (int h = 0; h < 2; ++h) {
            float lo, hi;
            asm("mov.b64 {%0,%1}, %2;" : "=f"(lo), "=f"(hi) : "l"(rs[mf][h]));
            float s = lo + hi;
            s += __shfl_xor_sync(0xffffffffu, s, 1);
            s += __shfl_xor_sync(0xffffffffu, s, 2);
            if ((lane & 3) == 0)
                s_part[wn][wm * 32 + mf * 16 + h * 8 + Rl] = s;
        }
    }
    __syncthreads();
    if (tid < TM)
        g_S[half * Nn + rowBase + tid] = s_part[0][tid] + s_part[1][tid];
}

// ---------------------------------------------------------------------------
// Finalize: loss_i = 10 + log(S_i) - pos_i; deterministic mean
// ---------------------------------------------------------------------------
__global__ void __launch_bounds__(128) final1_kernel() {
    __shared__ float sh[128];
    const int r = blockIdx.x * 128 + threadIdx.x;
    const float S = g_S[r] + g_S[Nn + r];
    sh[threadIdx.x] = 10.0f + logf(S) - g_pos[r];
    __syncthreads();
    #pragma unroll
    for (int o = 64; o; o >>= 1) {
        if (threadIdx.x < o) sh[threadIdx.x] += sh[threadIdx.x + o];
        __syncthreads();
    }
    if (threadIdx.x == 0) g_partial[blockIdx.x] = sh[0];
}

__global__ void __launch_bounds__(64) final2_kernel(float* __restrict__ out) {
    __shared__ float sh[64];
    sh[threadIdx.x] = g_partial[threadIdx.x];
    __syncthreads();
    #pragma unroll
    for (int o = 32; o; o >>= 1) {
        if (threadIdx.x < o) sh[threadIdx.x] += sh[threadIdx.x + o];
        __syncthreads();
    }
    if (threadIdx.x == 0) out[0] = sh[0] * (1.0f / (float)Nn);
}

// ---------------------------------------------------------------------------
extern "C" void kernel_launch(void* const* d_in, const int* in_sizes, int n_in,
                              void* d_out, int out_size) {
    const float* x = (const float*)d_in[0];
    float* out = (float*)d_out;
    (void)in_sizes; (void)n_in; (void)out_size;

    const int dyn = 3 * 32768;   // A + B0 + B1
    cudaFuncSetAttribute(ntxent_mma_kernel,
                         cudaFuncAttributeMaxDynamicSharedMemorySize, dyn);

    normalize_kernel<<<Nn / 8, dim3(32, 8)>>>(x);
    pos_kernel<<<Nn / 8, 256>>>();
    ntxent_mma_kernel<<<NRB * NHALF, 256, dyn>>>();
    final1_kernel<<<NRB, 128>>>();
    final2_kernel<<<1, 64>>>(out);
}

// round 13
// speedup vs baseline: 8.5875x; 1.4433x over previous
#include <cuda_runtime.h>
#include <cuda_bf16.h>
#include <cstdint>
#include <math.h>

#define Nn 8192
#define Dd 128
#define NB 64                 // 128-row blocks
#define NT (NB * (NB + 1) / 2)   // 2080 lower-triangle tiles
#define TPC 16                // tiles per CTA
#define GRID_MAIN (NT / TPC)  // 130

// __device__ globals (allocation-free scratch)
__device__ __nv_bfloat16  g_zb[Nn * Dd];          // normalized rows, bf16
__device__ float          g_acc[NB * NB * 128];   // [K][Q][r] partial sums, 2MB
__device__ float          g_pos[Nn];
__device__ float          g_partial[NB];

// ---------------------------------------------------------------------------
// helpers (base-sm_103-safe PTX only)
// ---------------------------------------------------------------------------
__device__ __forceinline__ uint32_t smem_u32(const void* p) {
    uint32_t a;
    asm("{ .reg .u64 t; cvta.to.shared.u64 t, %1; cvt.u32.u64 %0, t; }"
        : "=r"(a) : "l"(p));
    return a;
}
__device__ __forceinline__ void cpasync16(uint32_t dst, const void* src) {
    asm volatile("cp.async.cg.shared.global [%0], [%1], 16;"
                 :: "r"(dst), "l"(src) : "memory");
}
__device__ __forceinline__ void ldsm4(uint32_t* r, uint32_t addr) {
    asm volatile("ldmatrix.sync.aligned.m8n8.x4.shared.b16 {%0,%1,%2,%3}, [%4];"
                 : "=r"(r[0]), "=r"(r[1]), "=r"(r[2]), "=r"(r[3]) : "r"(addr));
}
__device__ __forceinline__ void mma16816(float* c, const uint32_t* a,
                                         uint32_t b0, uint32_t b1) {
    asm volatile(
        "mma.sync.aligned.m16n8k16.row.col.f32.bf16.bf16.f32 "
        "{%0,%1,%2,%3}, {%4,%5,%6,%7}, {%8,%9}, {%0,%1,%2,%3};"
        : "+f"(c[0]), "+f"(c[1]), "+f"(c[2]), "+f"(c[3])
        : "r"(a[0]), "r"(a[1]), "r"(a[2]), "r"(a[3]), "r"(b0), "r"(b1));
}
__device__ __forceinline__ unsigned long long pack2(float a, float b) {
    unsigned long long r;
    asm("mov.b64 %0, {%1,%2};" : "=l"(r) : "f"(a), "f"(b));
    return r;
}

// ---------------------------------------------------------------------------
// Kernel 1: normalize rows -> bf16, plus exact fp32 positive-pair logits
// ---------------------------------------------------------------------------
__global__ void __launch_bounds__(256) normpos_kernel(const float* __restrict__ x) {
    const int row  = blockIdx.x * 8 + threadIdx.y;
    const int lane = threadIdx.x;
    const int prow = (row + Nn / 2) & (Nn - 1);
    float4 v = reinterpret_cast<const float4*>(x)[row * 32 + lane];
    float4 u = reinterpret_cast<const float4*>(x)[prow * 32 + lane];
    float sv = v.x * v.x + v.y * v.y + v.z * v.z + v.w * v.w;
    float su = u.x * u.x + u.y * u.y + u.z * u.z + u.w * u.w;
    float dd = v.x * u.x + v.y * u.y + v.z * u.z + v.w * u.w;
    #pragma unroll
    for (int o = 16; o; o >>= 1) {
        sv += __shfl_xor_sync(0xffffffffu, sv, o);
        su += __shfl_xor_sync(0xffffffffu, su, o);
        dd += __shfl_xor_sync(0xffffffffu, dd, o);
    }
    const float nv = fmaxf(sqrtf(sv), 1e-8f);
    const float nu = fmaxf(sqrtf(su), 1e-8f);
    const float inv = 1.0f / nv;
    __nv_bfloat162 b0 = __floats2bfloat162_rn(v.x * inv, v.y * inv);
    __nv_bfloat162 b1 = __floats2bfloat162_rn(v.z * inv, v.w * inv);
    uint2 w;
    w.x = *reinterpret_cast<uint32_t*>(&b0);
    w.y = *reinterpret_cast<uint32_t*>(&b1);
    reinterpret_cast<uint2*>(g_zb)[row * 32 + lane] = w;
    if (lane == 0) g_pos[row] = 10.0f * dd / (nv * nu);
}

// ---------------------------------------------------------------------------
// Main: symmetric lower-triangle tiles, mma.sync bf16 + packed-exp2 epilogue
// ---------------------------------------------------------------------------
struct EC {
    unsigned long long C1, C0, MG, N1, P5, P4, P3, P2, P1, P0;
};

// rsum += e; csum += e; e = exp(10*x - 10) (2-wide). Optionally mask diag.
template <bool MASKED>
__device__ __forceinline__ void expacc2(float x0, float x1,
                                        unsigned long long& rsum,
                                        unsigned long long& csum,
                                        int R, int C, const EC& c) {
    unsigned long long v2 = pack2(x0, x1);
    unsigned long long t2, zi2, fzi2, f2, p2, r2;
    asm("fma.rn.f32x2 %0, %1, %2, %3;" : "=l"(t2)  : "l"(v2),   "l"(c.C1), "l"(c.C0));
    asm("add.rn.f32x2 %0, %1, %2;"     : "=l"(zi2) : "l"(t2),   "l"(c.MG));
    asm("fma.rn.f32x2 %0, %1, %2, %3;" : "=l"(fzi2): "l"(c.MG), "l"(c.N1), "l"(zi2));
    asm("fma.rn.f32x2 %0, %1, %2, %3;" : "=l"(f2)  : "l"(fzi2), "l"(c.N1), "l"(t2));
    asm("fma.rn.f32x2 %0, %1, %2, %3;" : "=l"(p2)  : "l"(c.P5), "l"(f2),   "l"(c.P4));
    asm("fma.rn.f32x2 %0, %1, %2, %3;" : "=l"(p2)  : "l"(p2),   "l"(f2),   "l"(c.P3));
    asm("fma.rn.f32x2 %0, %1, %2, %3;" : "=l"(p2)  : "l"(p2),   "l"(f2),   "l"(c.P2));
    asm("fma.rn.f32x2 %0, %1, %2, %3;" : "=l"(p2)  : "l"(p2),   "l"(f2),   "l"(c.P1));
    asm("fma.rn.f32x2 %0, %1, %2, %3;" : "=l"(p2)  : "l"(p2),   "l"(f2),   "l"(c.P0));
    uint32_t zlo, zhi, plo, phi;
    asm("mov.b64 {%0,%1}, %2;" : "=r"(zlo), "=r"(zhi) : "l"(zi2));
    asm("mov.b64 {%0,%1}, %2;" : "=r"(plo), "=r"(phi) : "l"(p2));
    uint32_t rlo = plo + (zlo << 23);
    uint32_t rhi = phi + (zhi << 23);
    if (MASKED) {
        if (R == C)     rlo = 0u;
        if (R == C + 1) rhi = 0u;
    }
    asm("mov.b64 %0, {%1,%2};" : "=l"(r2) : "r"(rlo), "r"(rhi));
    asm("add.rn.f32x2 %0, %1, %2;" : "=l"(rsum) : "l"(rsum), "l"(r2));
    asm("add.rn.f32x2 %0, %1, %2;" : "=l"(csum) : "l"(csum), "l"(r2));
}

// 128x128 bf16 tile (row-major) -> swizzled smem (chunk c ^= row&7)
__device__ __forceinline__ void load_tile(uint32_t sbase,
                                          const __nv_bfloat16* src, int tid) {
    #pragma unroll
    for (int p = 0; p < 8; ++p) {
        int idx = p * 256 + tid;
        int r = idx >> 4;
        int c = idx & 15;
        cpasync16(sbase + (uint32_t)(r * 256 + ((c ^ (r & 7)) << 4)),
                  (const void*)(src + r * Dd + c * 8));
    }
}
__device__ __forceinline__ uint32_t tile_addr(uint32_t sbase, int row, int ch) {
    return sbase + (uint32_t)(row * 256 + ((ch ^ (row & 7)) << 4));
}

__global__ void __launch_bounds__(256, 1) ntxent_sym_kernel() {
    extern __shared__ __align__(16) unsigned char dyn[];
    __shared__ float sRow[2][128];
    __shared__ float sCol[2][4][64];

    const int tid  = threadIdx.x;
    const int w    = tid >> 5;
    const int lane = tid & 31;
    const int wm   = w & 3;
    const int wn   = w >> 2;
    const uint32_t sbase = smem_u32(dyn);   // 2 stages x (A 32KB + B 32KB)

    // decode first tile id -> (I, J), J <= I
    int t0 = blockIdx.x * TPC;
    int I = 0, base = 0;
    while (base + I + 1 <= t0) { base += I + 1; ++I; }
    int J = t0 - base;

    load_tile(sbase, g_zb + (size_t)I * 128 * Dd, tid);
    load_tile(sbase + 32768u, g_zb + (size_t)J * 128 * Dd, tid);
    asm volatile("cp.async.commit_group;" ::: "memory");

    EC c;
    const float L = 14.4269504088896341f;
    c.C1 = pack2(L, L);   c.C0 = pack2(-L, -L);
    c.MG = pack2(12582912.0f, 12582912.0f);
    c.N1 = pack2(-1.0f, -1.0f);
    c.P5 = pack2(1.33335581e-3f, 1.33335581e-3f);
    c.P4 = pack2(9.61812911e-3f, 9.61812911e-3f);
    c.P3 = pack2(5.55041087e-2f, 5.55041087e-2f);
    c.P2 = pack2(2.40226507e-1f, 2.40226507e-1f);
    c.P1 = pack2(6.93147181e-1f, 6.93147181e-1f);
    c.P0 = pack2(1.0f, 1.0f);

    int Icur = I, Jcur = J;
    for (int i = 0; i < TPC; ++i) {
        int In = Icur, Jn = Jcur + 1;
        if (Jn > In) { ++In; Jn = 0; }
        if (i + 1 < TPC) {
            uint32_t sb = sbase + (uint32_t)(((i + 1) & 1) * 65536);
            load_tile(sb, g_zb + (size_t)In * 128 * Dd, tid);
            load_tile(sb + 32768u, g_zb + (size_t)Jn * 128 * Dd, tid);
            asm volatile("cp.async.commit_group;" ::: "memory");
            asm volatile("cp.async.wait_group 1;" ::: "memory");
        } else {
            asm volatile("cp.async.wait_group 0;" ::: "memory");
        }
        __syncthreads();   // tile i data visible; sRow/sCol of tile i-1 consumed

        const uint32_t sA = sbase + (uint32_t)((i & 1) * 65536);
        const uint32_t sB = sA + 32768u;

        uint32_t Af[2][8][4];
        #pragma unroll
        for (int mf = 0; mf < 2; ++mf) {
            const int arow = wm * 32 + mf * 16 + (lane & 15);
            #pragma unroll
            for (int k = 0; k < 8; ++k)
                ldsm4(Af[mf][k], tile_addr(sA, arow, 2 * k + (lane >> 4)));
        }

        unsigned long long rs[2][2], ct[4][2];
        #pragma unroll
        for (int a = 0; a < 2; ++a) { rs[a][0] = 0ull; rs[a][1] = 0ull; }
        #pragma unroll
        for (int a = 0; a < 4; ++a) { ct[a][0] = 0ull; ct[a][1] = 0ull; }

        const bool diagT = (Icur == Jcur);
        const int Rl = lane >> 2;
        const int Cl = (lane & 3) * 2;

        #pragma unroll
        for (int p = 0; p < 4; ++p) {
            float acc[2][2][4];
            #pragma unroll
            for (int a = 0; a < 2; ++a)
                #pragma unroll
                for (int b = 0; b < 2; ++b)
                    acc[a][b][0] = acc[a][b][1] = acc[a][b][2] = acc[a][b][3] = 0.0f;

            const int brow = wn * 64 + p * 16 + (lane & 15);
            #pragma unroll
            for (int k = 0; k < 8; ++k) {
                uint32_t b[4];
                ldsm4(b, tile_addr(sB, brow, 2 * k + (lane >> 4)));
                mma16816(acc[0][0], Af[0][k], b[0], b[2]);
                mma16816(acc[0][1], Af[0][k], b[1], b[3]);
                mma16816(acc[1][0], Af[1][k], b[0], b[2]);
                mma16816(acc[1][1], Af[1][k], b[1], b[3]);
            }

            #pragma unroll
            for (int mf = 0; mf < 2; ++mf) {
                #pragma unroll
                for (int nh = 0; nh < 2; ++nh) {
                    const float* a = acc[mf][nh];
                    if (diagT) {
                        const int R0 = wm * 32 + mf * 16 + Rl;       // same block
                        const int C0 = wn * 64 + p * 16 + nh * 8 + Cl;
                        expacc2<true >(a[0], a[1], rs[mf][0], ct[p][nh], R0,     C0, c);
                        expacc2<true >(a[2], a[3], rs[mf][1], ct[p][nh], R0 + 8, C0, c);
                    } else {
                        expacc2<false>(a[0], a[1], rs[mf][0], ct[p][nh], 0, 0, c);
                        expacc2<false>(a[2], a[3], rs[mf][1], ct[p][nh], 0, 0, c);
                    }
                }
            }
        }

        // ---- row sums: reduce over lane&3, combine wn halves via smem ----
        #pragma unroll
        for (int mf = 0; mf < 2; ++mf) {
            #pragma unroll
            for (int h = 0; h < 2; ++h) {
                float lo, hi;
                asm("mov.b64 {%0,%1}, %2;" : "=f"(lo), "=f"(hi) : "l"(rs[mf][h]));
                float s = lo + hi;
                s += __shfl_xor_sync(0xffffffffu, s, 1);
                s += __shfl_xor_sync(0xffffffffu, s, 2);
                if ((lane & 3) == 0)
                    sRow[wn][wm * 32 + mf * 16 + h * 8 + Rl] = s;
            }
        }
        // ---- col sums: reduce over lane>>2 (rows), stash per (wn, wm) ----
        #pragma unroll
        for (int p = 0; p < 4; ++p) {
            #pragma unroll
            for (int nh = 0; nh < 2; ++nh) {
                float lo, hi;
                asm("mov.b64 {%0,%1}, %2;" : "=f"(lo), "=f"(hi) : "l"(ct[p][nh]));
                #pragma unroll
                for (int o = 4; o <= 16; o <<= 1) {
                    lo += __shfl_xor_sync(0xffffffffu, lo, o);
                    hi += __shfl_xor_sync(0xffffffffu, hi, o);
                }
                if (lane < 4) {
                    sCol[wn][wm][p * 16 + nh * 8 + lane * 2]     = lo;
                    sCol[wn][wm][p * 16 + nh * 8 + lane * 2 + 1] = hi;
                }
            }
        }
        __syncthreads();

        if (tid < 128) {
            g_acc[((size_t)Icur * NB + Jcur) * 128 + tid] =
                sRow[0][tid] + sRow[1][tid];
        } else if (!diagT) {
            const int cx = tid - 128;
            const float v = sCol[cx >> 6][0][cx & 63] + sCol[cx >> 6][1][cx & 63]
                          + sCol[cx >> 6][2][cx & 63] + sCol[cx >> 6][3][cx & 63];
            g_acc[((size_t)Jcur * NB + Icur) * 128 + cx] = v;
        }
        Icur = In; Jcur = Jn;
    }
}

// ---------------------------------------------------------------------------
// Gather + loss: S[r] = sum_Q g_acc[K][Q][r]; loss = 10 + log S - pos
// ---------------------------------------------------------------------------
__global__ void __launch_bounds__(128) gather_kernel() {
    __shared__ float sh[128];
    const int K = blockIdx.x, r = threadIdx.x;
    const float* pa = g_acc + (size_t)K * NB * 128 + r;
    float s = 0.0f;
    #pragma unroll
    for (int Q = 0; Q < NB; ++Q) s += pa[(size_t)Q * 128];
    sh[r] = 10.0f + logf(s) - g_pos[K * 128 + r];
    __syncthreads();
    #pragma unroll
    for (int o = 64; o; o >>= 1) {
        if (r < o) sh[r] += sh[r + o];
        __syncthreads();
    }
    if (r == 0) g_partial[K] = sh[0];
}

__global__ void __launch_bounds__(64) final2_kernel(float* __restrict__ out) {
    __shared__ float sh[64];
    sh[threadIdx.x] = g_partial[threadIdx.x];
    __syncthreads();
    #pragma unroll
    for (int o = 32; o; o >>= 1) {
        if (threadIdx.x < o) sh[threadIdx.x] += sh[threadIdx.x + o];
        __syncthreads();
    }
    if (threadIdx.x == 0) out[0] = sh[0] * (1.0f / (float)Nn);
}

// ---------------------------------------------------------------------------
extern "C" void kernel_launch(void* const* d_in, const int* in_sizes, int n_in,
                              void* d_out, int out_size) {
    const float* x = (const float*)d_in[0];
    float* out = (float*)d_out;
    (void)in_sizes; (void)n_in; (void)out_size;

    const int dyn = 2 * 65536;   // 2 stages x (A + B)
    cudaFuncSetAttribute(ntxent_sym_kernel,
                         cudaFuncAttributeMaxDynamicSharedMemorySize, dyn);

    normpos_kernel<<<Nn / 8, dim3(32, 8)>>>(x);
    ntxent_sym_kernel<<<GRID_MAIN, 256, dyn>>>();
    gather_kernel<<<NB, 128>>>();
    final2_kernel<<<1, 64>>>(out);
}